// round 11
// baseline (speedup 1.0000x reference)
#include <cuda_runtime.h>
#include <cuda_bf16.h>
#include <cstdint>

// ChaosModulator: per-channel nonlinear recurrence over t.
//   sigma = 3.5*z*(1-z) + 0.5*x
//   z'    = 0.5*z + 0.5*sigmoid(2*sigma)     (clip(0,1) is a provable no-op)
//   u     = 0.5*x + (z' - 0.5)
//
// R11: occupancy was launch-size-capped (131072 threads = 27.7 warps/SM).
// Double parallelism: S=16 chunks of 256 (was 8x512). 262144 threads ->
// ~40 warps/SM (reg-capped at 10 blocks). DRAM duty has tracked occupancy
// ~1.5x in every round; warmup traffic cost is only +6%.
// Warp-autonomous 3-phase smem staging (R7): warp owns 2 channels x 16
// chunks = 32 rows = one contiguous 32KB x-span (addr = row*CHUNK + t,
// T = 16*CHUNK). XOR float4 swizzle (c4 ^ (r&7), 128B rows) -> conflict-free
// STS/LDS. __syncwarp only; WARM=64 from z=0.5 (contraction erases state).

#define WARM  64
#define TS    32
#define S_CH  16

__device__ __forceinline__ float ex2_approx(float v) {
    float y; asm("ex2.approx.f32 %0, %1;" : "=f"(y) : "f"(v)); return y;
}
__device__ __forceinline__ float rcp_approx(float v) {
    float y; asm("rcp.approx.f32 %0, %1;" : "=f"(y) : "f"(v)); return y;
}

// sigma_tilde = -2*log2(e)*sigma = K1*(z - z^2) + K2*x
#define K1 (-10.098865286222744f)  /* -7 * log2(e) */
#define K2 (-1.4426950408889634f)  /* -1 * log2(e) */

__device__ __forceinline__ float step_z(float z, float xx) {
    float p  = fmaf(-z, z, z);          // z - z^2
    float tt = fmaf(K1, p, K2 * xx);
    float e  = ex2_approx(tt);
    float r  = rcp_approx(1.0f + e);    // sigmoid(2*sigma)
    return fmaf(0.5f, r, 0.5f * z);
}

__global__ void __launch_bounds__(128, 10)
chaos_kernel(const float* __restrict__ x,
             const float* __restrict__ z0,
             float* __restrict__ u,
             int n_ch, int T)
{
    // Per-warp slab: 32 rows x 8 float4 (128B row stride).
    __shared__ float4 sbuf[4][32][8];

    const int tid  = threadIdx.x;
    const int wid  = tid >> 5;
    const int lane = tid & 31;

    const int CHUNK = T / S_CH;               // 256
    const int NT    = CHUNK / TS;             // 8 tiles

    // Warp owns channels [ch0, ch0+2): one contiguous 32KB span of x.
    const int ch0 = blockIdx.x * 8 + wid * 2;
    const char* __restrict__ gx = (const char*)(x + (size_t)ch0 * T);
    char* __restrict__       gu = (char*)(u + (size_t)ch0 * T);

    const int l3 = lane >> 3;                 // 0..3  (loader row group)
    const int c4 = lane & 7;                  // float4 column group

    float4 (*sb)[8] = sbuf[wid];

    // Loader base byte-offset for row l3 (+4 rows per j => +4*CHUNK floats).
    const uint32_t off0 = (uint32_t)((l3 * CHUNK + c4 * 4) * 4);
    const uint32_t JSTR = (uint32_t)(4 * CHUNK * 4);   // 4096 for CHUNK=256

    // Compute role: row = lane => channel ch0 + (lane>>4), chunk s = lane&15.
    const int s    = lane & (S_CH - 1);
    const int ckey = lane & 7;                // swizzle key (r&7)
    float z = (s == 0) ? z0[ch0 + (lane >> 4)] : 0.5f;

    // ---- Warmup: 2 tiles of 32 steps (chunk-0 rows skip) ----
    for (int w = 0; w < WARM / TS; ++w) {
        const int tb = (-WARM + w * TS) * 4;          // byte offset in t
        uint32_t off = off0;
#pragma unroll
        for (int j = 0; j < 8; ++j, off += JSTR) {
            int r     = l3 + 4 * j;                   // row 0..31
            int key   = r & 7;                        // bank swizzle key
            int key16 = r & (S_CH - 1);               // chunk id of row
            if (key16 != 0) {
                float4 v = *(const float4*)(gx + off + tb);
                sb[r][c4 ^ key] = v;
            }
        }
        __syncwarp();
        if (s != 0) {
#pragma unroll
            for (int c = 0; c < 8; ++c) {
                float4 v = sb[lane][c ^ ckey];
                z = step_z(z, v.x); z = step_z(z, v.y);
                z = step_z(z, v.z); z = step_z(z, v.w);
            }
        }
        __syncwarp();
    }

    // ---- Main: per-tile load -> compute in place -> store, warp-private ----
    for (int tile = 0; tile < NT; ++tile) {
        const uint32_t tb = (uint32_t)(tile * TS * 4);

        {
            uint32_t off = off0 + tb;
#pragma unroll
            for (int j = 0; j < 8; ++j, off += JSTR) {
                int r   = l3 + 4 * j;
                int key = r & 7;
                float4 v = *(const float4*)(gx + off);
                sb[r][c4 ^ key] = v;
            }
        }
        __syncwarp();

#pragma unroll
        for (int c = 0; c < 8; ++c) {
            float4 v = sb[lane][c ^ ckey];
            float4 o; float h;
            h = fmaf(0.5f, v.x, -0.5f); z = step_z(z, v.x); o.x = h + z;
            h = fmaf(0.5f, v.y, -0.5f); z = step_z(z, v.y); o.y = h + z;
            h = fmaf(0.5f, v.z, -0.5f); z = step_z(z, v.z); o.z = h + z;
            h = fmaf(0.5f, v.w, -0.5f); z = step_z(z, v.w); o.w = h + z;
            sb[lane][c ^ ckey] = o;
        }
        __syncwarp();

        {
            uint32_t off = off0 + tb;
#pragma unroll
            for (int j = 0; j < 8; ++j, off += JSTR) {
                int r   = l3 + 4 * j;
                int key = r & 7;
                float4 v = sb[r][c4 ^ key];
                *(float4*)(gu + off) = v;
            }
        }
        __syncwarp();                        // protect smem before next STS
    }
}

extern "C" void kernel_launch(void* const* d_in, const int* in_sizes, int n_in,
                              void* d_out, int out_size)
{
    const float* x  = (const float*)d_in[0];   // (b, c, t) f32
    const float* z0 = (const float*)d_in[1];   // (b, c)    f32
    float* u = (float*)d_out;

    int n_ch = in_sizes[1];            // b*c = 16384
    int T    = in_sizes[0] / n_ch;     // 4096

    int grid = n_ch / 8;               // 8 channels per 128-thread block
    chaos_kernel<<<grid, 128>>>(x, z0, u, n_ch, T);
}

// round 13
// speedup vs baseline: 1.0271x; 1.0271x over previous
#include <cuda_runtime.h>
#include <cuda_bf16.h>
#include <cstdint>

// ChaosModulator: per-channel nonlinear recurrence over t.
//   sigma = 3.5*z*(1-z) + 0.5*x
//   z'    = 0.5*z + 0.5*sigmoid(2*sigma)     (clip(0,1) is a provable no-op)
//   u     = 0.5*x + (z' - 0.5)
//
// R13 = R12 with the cp.async smem swizzle FIXED. R12 computed the loader's
// swizzled column as ((c4^l3)<<4) + (j&1)*64; correct form XORs the (j&1)
// term into bit 6 (carry into bit 7 jumped rows / overran the slab -> the
// illegal memory access). Structure: S=8 chunks of 512, WARM=64, warp owns
// 4 channels x 8 chunks = 32 rows = contiguous 64KB x-span; warp-private
// double-buffered LDGSTS keeps tile t+1 in flight during compute+store of
// tile t (wait_group 1). __syncwarp only; XOR float4 swizzle -> conflict-free.

#define WARM  64
#define TS    32

__device__ __forceinline__ float ex2_approx(float v) {
    float y; asm("ex2.approx.f32 %0, %1;" : "=f"(y) : "f"(v)); return y;
}
__device__ __forceinline__ float rcp_approx(float v) {
    float y; asm("rcp.approx.f32 %0, %1;" : "=f"(y) : "f"(v)); return y;
}

// sigma_tilde = -2*log2(e)*sigma = K1*(z - z^2) + K2*x
#define K1 (-10.098865286222744f)  /* -7 * log2(e) */
#define K2 (-1.4426950408889634f)  /* -1 * log2(e) */

__device__ __forceinline__ float step_z(float z, float xx) {
    float p  = fmaf(-z, z, z);          // z - z^2
    float tt = fmaf(K1, p, K2 * xx);
    float e  = ex2_approx(tt);
    float r  = rcp_approx(1.0f + e);    // sigmoid(2*sigma)
    return fmaf(0.5f, r, 0.5f * z);
}

__device__ __forceinline__ void cpasync16(uint32_t s, const void* g) {
    asm volatile("cp.async.cg.shared.global [%0], [%1], 16;" :: "r"(s), "l"(g));
}
#define CP_COMMIT() asm volatile("cp.async.commit_group;" ::: "memory")
#define CP_WAIT0()  asm volatile("cp.async.wait_group 0;"  ::: "memory")
#define CP_WAIT1()  asm volatile("cp.async.wait_group 1;"  ::: "memory")

__global__ void __launch_bounds__(128, 7)
chaos_kernel(const float* __restrict__ x,
             const float* __restrict__ z0,
             float* __restrict__ u,
             int n_ch, int T)
{
    // Per-warp: 2 slabs of 32 rows x 8 float4 (128B row stride). 32KB/block.
    __shared__ float4 sbuf[4][2][32][8];

    const int tid  = threadIdx.x;
    const int wid  = tid >> 5;
    const int lane = tid & 31;

    const int CHUNK = T >> 3;                 // 512 (S = 8 chunks)
    const int NT    = CHUNK / TS;             // 16 tiles

    // Warp owns channels [ch0, ch0+4): one contiguous 64KB span of x.
    const int ch0 = blockIdx.x * 16 + wid * 4;
    const char* __restrict__ gx = (const char*)(x + (size_t)ch0 * T);
    char* __restrict__       gu = (char*)(u + (size_t)ch0 * T);

    const int l3 = lane >> 3;                 // 0..3  (loader row group)
    const int c4 = lane & 7;                  // float4 column group

    float4 (*sb0)[8] = sbuf[wid][0];
    float4 (*sb1)[8] = sbuf[wid][1];

    const uint32_t slab0 = (uint32_t)__cvta_generic_to_shared(&sb0[0][0]);
    const uint32_t slab1 = slab0 + 32 * 8 * 16;       // +4096

    // Loader smem offset for row r = l3 + 4j, swizzle key = r&7 = l3|4(j&1):
    //   soff(j) = r*128 + ((c4 ^ key)<<4)
    //           = l3*128 + j*512 + ( ((c4^l3) ^ ((j&1)<<2)) << 4 )
    // (computed per-j below; j is a compile-time constant after unroll)
    const uint32_t lrow = (uint32_t)(l3 * 128);
    const uint32_t lcol = (uint32_t)(c4 ^ l3);

    // Gmem byte offset: row l3 base; +4 rows per j => +4*CHUNK floats.
    const uint32_t off0 = (uint32_t)((l3 * CHUNK + c4 * 4) * 4);
    const uint32_t JSTR = (uint32_t)(4 * CHUNK * 4);  // 8192

    // Compute role: row = lane, channel = ch0 + l3, chunk s = lane&7.
    const int s    = lane & 7;
    const int ckey = lane & 7;
    float z = (s == 0) ? z0[ch0 + l3] : 0.5f;

    // ---- Warmup: 2 tiles of 32 steps via slab0 (chunk-0 rows skip) ----
    for (int w = 0; w < WARM / TS; ++w) {
        const int tb = (-WARM + w * TS) * 4;          // byte offset in t
#pragma unroll
        for (int j = 0; j < 8; ++j) {
            int key = l3 | ((j & 1) << 2);            // r&7 for r=l3+4j
            uint32_t soff = lrow + j * 512 + ((lcol ^ ((j & 1) << 2)) << 4);
            if (key != 0)
                cpasync16(slab0 + soff, gx + off0 + tb + j * JSTR);
        }
        CP_COMMIT(); CP_WAIT0();
        __syncwarp();
        if (s != 0) {
#pragma unroll
            for (int c = 0; c < 8; ++c) {
                float4 v = sb0[lane][c ^ ckey];
                z = step_z(z, v.x); z = step_z(z, v.y);
                z = step_z(z, v.z); z = step_z(z, v.w);
            }
        }
        __syncwarp();
    }

    // ---- Prologue: tile 0 -> slab0 ----
#pragma unroll
    for (int j = 0; j < 8; ++j) {
        uint32_t soff = lrow + j * 512 + ((lcol ^ ((j & 1) << 2)) << 4);
        cpasync16(slab0 + soff, gx + off0 + j * JSTR);
    }
    CP_COMMIT();

    // ---- Main pipeline: prefetch t+1 while computing/storing t ----
    uint32_t curs = slab0, nxts = slab1;
    for (int tile = 0; tile < NT; ++tile) {
        const uint32_t tb = (uint32_t)(tile * TS * 4);

        if (tile + 1 < NT) {
            const uint32_t tb1 = tb + TS * 4;
#pragma unroll
            for (int j = 0; j < 8; ++j) {
                uint32_t soff = lrow + j * 512 + ((lcol ^ ((j & 1) << 2)) << 4);
                cpasync16(nxts + soff, gx + off0 + tb1 + j * JSTR);
            }
            CP_COMMIT();
            CP_WAIT1();                  // tile t landed; t+1 in flight
        } else {
            CP_WAIT0();                  // last tile: wait it fully
        }
        __syncwarp();

        // Compute in place: x tile -> u tile (own row only)
        {
            float4 (*bb)[8] = (curs == slab0) ? sb0 : sb1;
#pragma unroll
            for (int c = 0; c < 8; ++c) {
                float4 v = bb[lane][c ^ ckey];
                float4 o; float h;
                h = fmaf(0.5f, v.x, -0.5f); z = step_z(z, v.x); o.x = h + z;
                h = fmaf(0.5f, v.y, -0.5f); z = step_z(z, v.y); o.y = h + z;
                h = fmaf(0.5f, v.z, -0.5f); z = step_z(z, v.z); o.z = h + z;
                h = fmaf(0.5f, v.w, -0.5f); z = step_z(z, v.w); o.w = h + z;
                bb[lane][c ^ ckey] = o;
            }
        }
        __syncwarp();

        // Coalesced store-out of tile t
        {
            float4 (*bb)[8] = (curs == slab0) ? sb0 : sb1;
#pragma unroll
            for (int j = 0; j < 8; ++j) {
                int r   = l3 + 4 * j;
                int key = l3 | ((j & 1) << 2);
                float4 v = bb[r][c4 ^ key];
                *(float4*)(gu + off0 + tb + j * JSTR) = v;
            }
        }
        __syncwarp();   // all store-reads of this slab done before the
                        // cp.async issued next iteration overwrites it

        uint32_t tmp = curs; curs = nxts; nxts = tmp;
    }
}

extern "C" void kernel_launch(void* const* d_in, const int* in_sizes, int n_in,
                              void* d_out, int out_size)
{
    const float* x  = (const float*)d_in[0];   // (b, c, t) f32
    const float* z0 = (const float*)d_in[1];   // (b, c)    f32
    float* u = (float*)d_out;

    int n_ch = in_sizes[1];            // b*c = 16384
    int T    = in_sizes[0] / n_ch;     // 4096

    int grid = n_ch / 16;              // 16 channels per 128-thread block
    chaos_kernel<<<grid, 128>>>(x, z0, u, n_ch, T);
}